// round 12
// baseline (speedup 1.0000x reference)
#include <cuda_runtime.h>
#include <math_constants.h>

#define BB 64
#define JJ 32
#define MM 160
#define NN 160
#define HW (MM * NN)   // 25600
#define NV4 (HW / 4)   // 6400 float4 per row
#define THREADS 256
#define NWARP (THREADS / 32)   // 8
#define NOBJ (BB * JJ) // 2048

__device__ float g_perobj[NOBJ];
__device__ unsigned int g_count = 0;

// Fused: per-(b,j) argmax + loss + last-block reduction.
// Heatmap loads use .cg (L1-bypass): the stream has zero reuse, so default
// L1 fills only lengthen the L1tex wavefront queue for all resident CTAs.
__global__ __launch_bounds__(THREADS) void argmax_loss_fused_kernel(
    const float* __restrict__ pred,
    const float* __restrict__ gt,
    const float* __restrict__ heatmap,
    float* __restrict__ out)
{
    const int bj = blockIdx.x;                 // 0 .. B*J-1
    const int tid = threadIdx.x;
    const float4* row = reinterpret_cast<const float4*>(heatmap + (size_t)bj * HW);

    // fmax-tree body: 3 FMNMX per float4, one predicated (best, i) update.
    // Track float4 index only; element resolved after the loop.
    float best = -CUDART_INF_F;
    int   bi   = tid;
    #pragma unroll 5
    for (int i = tid; i < NV4; i += THREADS) {
        float4 v = __ldcg(&row[i]);            // L1-bypass, normal L2
        float m = fmaxf(fmaxf(v.x, v.y), fmaxf(v.z, v.w));
        if (m > best) { best = m; bi = i; }    // strict > keeps earliest float4
    }

    // Resolve element within the winning float4 (first equal wins;
    // fmaxf returns operand bits exactly, so == matches).
    int bidx;
    {
        float4 v = __ldcg(&row[bi]);
        int e = 3;
        if (v.z == best) e = 2;
        if (v.y == best) e = 1;
        if (v.x == best) e = 0;
        bidx = bi * 4 + e;
    }

    // Warp-level reduction: 5 shfl steps on (val, idx), first-index tie-break.
    #pragma unroll
    for (int off = 16; off > 0; off >>= 1) {
        float ov = __shfl_down_sync(0xFFFFFFFFu, best, off);
        int   oi = __shfl_down_sync(0xFFFFFFFFu, bidx, off);
        if (ov > best || (ov == best && oi < bidx)) { best = ov; bidx = oi; }
    }

    __shared__ float svals[NWARP];
    __shared__ int   sidx[NWARP];
    const int warp = tid >> 5;
    const int lane = tid & 31;
    if (lane == 0) { svals[warp] = best; sidx[warp] = bidx; }
    __syncthreads();

    // Warps 1..7 retire early; warp 0 runs the tail.
    if (warp != 0) return;

    // Merge the 8 warp winners in-warp (lanes 0..7 hold candidates).
    {
        float mv = (lane < NWARP) ? svals[lane] : -CUDART_INF_F;
        int   mi = (lane < NWARP) ? sidx[lane]  : 0x7FFFFFFF;
        #pragma unroll
        for (int off = 4; off > 0; off >>= 1) {
            float ov = __shfl_down_sync(0xFFFFFFFFu, mv, off);
            int   oi = __shfl_down_sync(0xFFFFFFFFu, mi, off);
            if (ov > mv || (ov == mv && oi < mi)) { mv = ov; mi = oi; }
        }
        best = mv;
        bidx = mi;
    }

    unsigned int old = 0;
    if (lane == 0) {
        int idx = bidx;
        float x = (float)(idx / MM);   // reference: idx // m
        float y = (float)(idx % MM);   // reference: idx %  m

        int b = bj / JJ;
        int j = bj % JJ;

        const float* g = gt + ((size_t)b * JJ + j) * 11;
        float g7 = g[7], g8 = g[8], g9 = g[9], g10 = g[10];
        bool valid = (g9 > 0.0f) && (g10 > 0.0f) && (g9 < (float)MM) && (g10 < (float)NN);

        // pred layout: (B, 9, J, 1) -> pred[((b*9 + c)*J) + j]
        const float* pb = pred + (size_t)b * 9 * JJ + j;
        float px = pb[7 * JJ];
        float py = pb[8 * JJ];

        float dx = g9 + g7 - x - px;
        float dy = g10 + g8 - y - py;
        float loss = dx * dx + dy * dy;

        float cls = 0.0f;
        #pragma unroll
        for (int c = 0; c < 7; c++) {
            float d = pb[c * JJ] - g[c];
            cls = fmaf(d, d, cls);
        }

        g_perobj[bj] = valid ? (cls + loss) : 0.0f;

        // Release-atomic: orders the g_perobj store before the count bump
        // without a per-block L1-flushing __threadfence().
        asm volatile("atom.release.gpu.add.u32 %0, [%1], 1;"
                     : "=r"(old) : "l"(&g_count) : "memory");
    }
    old = __shfl_sync(0xFFFFFFFFu, old, 0);

    if (old == NOBJ - 1) {
        // Last block: acquire side (one fence per LAUNCH, not per block).
        __threadfence();
        // 32 lanes each sum 2 batches of 32 per-joint losses.
        #pragma unroll
        for (int r = 0; r < 2; r++) {
            int b = lane * 2 + r;
            float s = 0.0f;
            #pragma unroll
            for (int j = 0; j < JJ; j++)
                s += __ldcg(&g_perobj[b * JJ + j]);
            out[b] = s;
        }
        if (lane == 0)
            g_count = 0;   // reset for next graph replay (deterministic)
    }
}

extern "C" void kernel_launch(void* const* d_in, const int* in_sizes, int n_in,
                              void* d_out, int out_size)
{
    const float* pred    = (const float*)d_in[0];
    const float* gt      = (const float*)d_in[1];
    const float* heatmap = (const float*)d_in[2];
    float* out = (float*)d_out;

    argmax_loss_fused_kernel<<<NOBJ, THREADS>>>(pred, gt, heatmap, out);
}

// round 13
// speedup vs baseline: 1.1088x; 1.1088x over previous
#include <cuda_runtime.h>
#include <math_constants.h>

#define BB 64
#define JJ 32
#define MM 160
#define NN 160
#define HW (MM * NN)   // 25600
#define THREADS 256
#define NWARP (THREADS / 32)   // 8
#define NOBJ (BB * JJ) // 2048

__device__ float g_perobj[NOBJ];
__device__ unsigned int g_batchcnt[BB];   // monotone: +JJ per launch, mod-32 epoch

// Fused argmax + loss, with DISTRIBUTED completion: 64 per-batch counters
// (32 arrivals each) instead of one global counter with 2048 serialized
// arrivals at the LTS atomic ALU. The 32nd finisher of a batch sums that
// batch's 32 losses warp-parallel and writes out[b] directly.
__global__ __launch_bounds__(THREADS) void argmax_loss_fused_kernel(
    const float* __restrict__ pred,
    const float* __restrict__ gt,
    const float* __restrict__ heatmap,
    float* __restrict__ out)
{
    const int bj = blockIdx.x;                 // 0 .. B*J-1
    const int tid = threadIdx.x;
    const float4* row = reinterpret_cast<const float4*>(heatmap + (size_t)bj * HW);

    float best = -CUDART_INF_F;
    int bidx = 0;

    // R3's best-measured body: 25 iters, ~5 loads in flight, serial chain.
    #pragma unroll 5
    for (int i = tid; i < HW / 4; i += THREADS) {
        float4 v = row[i];
        int base = i * 4;
        // strictly-greater keeps the earliest index within a thread
        if (v.x > best) { best = v.x; bidx = base; }
        if (v.y > best) { best = v.y; bidx = base + 1; }
        if (v.z > best) { best = v.z; bidx = base + 2; }
        if (v.w > best) { best = v.w; bidx = base + 3; }
    }

    // Warp-level reduction: 5 shfl steps on (val, idx), first-index tie-break.
    #pragma unroll
    for (int off = 16; off > 0; off >>= 1) {
        float ov = __shfl_down_sync(0xFFFFFFFFu, best, off);
        int   oi = __shfl_down_sync(0xFFFFFFFFu, bidx, off);
        if (ov > best || (ov == best && oi < bidx)) { best = ov; bidx = oi; }
    }

    __shared__ float svals[NWARP];
    __shared__ int   sidx[NWARP];
    const int warp = tid >> 5;
    const int lane = tid & 31;
    if (lane == 0) { svals[warp] = best; sidx[warp] = bidx; }
    __syncthreads();

    // Warps 1..7 retire early; warp 0 runs the tail.
    if (warp != 0) return;

    // Merge the 8 warp winners in-warp (lanes 0..7 hold candidates).
    {
        float mv = (lane < NWARP) ? svals[lane] : -CUDART_INF_F;
        int   mi = (lane < NWARP) ? sidx[lane]  : 0x7FFFFFFF;
        #pragma unroll
        for (int off = 4; off > 0; off >>= 1) {
            float ov = __shfl_down_sync(0xFFFFFFFFu, mv, off);
            int   oi = __shfl_down_sync(0xFFFFFFFFu, mi, off);
            if (ov > mv || (ov == mv && oi < mi)) { mv = ov; mi = oi; }
        }
        best = mv;
        bidx = mi;
    }

    const int b = bj / JJ;
    const int j = bj % JJ;

    unsigned int rc = 0;
    if (lane == 0) {
        int idx = bidx;
        float x = (float)(idx / MM);   // reference: idx // m
        float y = (float)(idx % MM);   // reference: idx %  m

        const float* g = gt + ((size_t)b * JJ + j) * 11;
        float g7 = g[7], g8 = g[8], g9 = g[9], g10 = g[10];
        bool valid = (g9 > 0.0f) && (g10 > 0.0f) && (g9 < (float)MM) && (g10 < (float)NN);

        // pred layout: (B, 9, J, 1) -> pred[((b*9 + c)*J) + j]
        const float* pb = pred + (size_t)b * 9 * JJ + j;
        float px = pb[7 * JJ];
        float py = pb[8 * JJ];

        float dx = g9 + g7 - x - px;
        float dy = g10 + g8 - y - py;
        float loss = dx * dx + dy * dy;

        float cls = 0.0f;
        #pragma unroll
        for (int c = 0; c < 7; c++) {
            float d = pb[c * JJ] - g[c];
            cls = fmaf(d, d, cls);
        }

        g_perobj[bj] = valid ? (cls + loss) : 0.0f;

        // acq_rel: releases my g_perobj store; if I'm the 32nd arrival for
        // this batch, acquires the other 31 rows' released stores.
        // 64 distinct addresses -> no single-address LTS serialization tail.
        asm volatile("atom.acq_rel.gpu.add.u32 %0, [%1], 1;"
                     : "=r"(rc) : "l"(&g_batchcnt[b]) : "memory");
    }
    rc = __shfl_sync(0xFFFFFFFFu, rc, 0);

    if ((rc & (JJ - 1)) == JJ - 1) {
        // 32nd finisher of batch b this launch: warp-parallel 32 -> 1 sum.
        float s = __ldcg(&g_perobj[b * JJ + lane]);
        #pragma unroll
        for (int off = 16; off > 0; off >>= 1)
            s += __shfl_down_sync(0xFFFFFFFFu, s, off);
        if (lane == 0) out[b] = s;
    }
}

extern "C" void kernel_launch(void* const* d_in, const int* in_sizes, int n_in,
                              void* d_out, int out_size)
{
    const float* pred    = (const float*)d_in[0];
    const float* gt      = (const float*)d_in[1];
    const float* heatmap = (const float*)d_in[2];
    float* out = (float*)d_out;

    argmax_loss_fused_kernel<<<NOBJ, THREADS>>>(pred, gt, heatmap, out);
}